// round 13
// baseline (speedup 1.0000x reference)
#include <cuda_runtime.h>
#include <math.h>
#include <stdint.h>

#define B_   64
#define NV   40000
#define P_   100
#define NJ   24
#define SKEL_OFF 7680000   // 64*40000*3
#define NBLK 2500
#define NROW 30

// ---------------- scratch (device globals; no allocation allowed) ----------------
__device__ float g_G1[B_ * NJ * 12];
__device__ float g_part[23 * 4 * B_ * 6];
__device__ int   g_done  = 0;   // grid ticket; returns to 0 after each replay
__device__ int   g_done2 = 0;   // finalizer count; returns to 0 after each replay

// ---------------- cp.async helpers ----------------
__device__ __forceinline__ void cp16(uint32_t dst, const void* src) {
    asm volatile("cp.async.cg.shared.global [%0], [%1], 16;" :: "r"(dst), "l"(src));
}
__device__ __forceinline__ void cp_commit() {
    asm volatile("cp.async.commit_group;");
}
template <int N>
__device__ __forceinline__ void cp_wait() {
    asm volatile("cp.async.wait_group %0;" :: "n"(N));
}

// ---------------- tf32 mma helpers ----------------
__device__ __forceinline__ uint32_t f2tf32(float f) {
    uint32_t u; asm("cvt.rna.tf32.f32 %0, %1;" : "=r"(u) : "f"(f)); return u;
}
__device__ __forceinline__ void mma_tf32(float c[4],
    uint32_t a0, uint32_t a1, uint32_t a2, uint32_t a3,
    uint32_t b0, uint32_t b1)
{
    asm volatile(
        "mma.sync.aligned.m16n8k8.row.col.f32.tf32.tf32.f32 "
        "{%0,%1,%2,%3},{%4,%5,%6,%7},{%8,%9},{%0,%1,%2,%3};"
        : "+f"(c[0]), "+f"(c[1]), "+f"(c[2]), "+f"(c[3])
        : "r"(a0), "r"(a1), "r"(a2), "r"(a3), "r"(b0), "r"(b1));
}

// ---------------- Kernel A1: gathered v_posed + per-chunk min/max ----------------
// grid (23, 4), block (32, 8)
__global__ __launch_bounds__(256) void k_joint_gather(
    const float* __restrict__ beta, const float* __restrict__ sd,
    const float* __restrict__ vt, const int* __restrict__ joint_idx)
{
    extern __shared__ float sm[];
    float* beta_s = sm;          // [64][100]
    float* sd_cs  = sm + 6400;   // [100][96]
    __shared__ int idxs[32];

    int j = blockIdx.x, ch = blockIdx.y;
    int tid = threadIdx.y * 32 + threadIdx.x;

    if (tid < 32) idxs[tid] = joint_idx[j * 128 + ch * 32 + tid];
    for (int i = tid; i < 6400; i += 256) beta_s[i] = beta[i];
    __syncthreads();

    for (int i = tid; i < 3200; i += 256) {
        int p = i >> 5, s = i & 31;
        size_t base = (size_t)p * 120000 + 3 * idxs[s];
        sd_cs[p * 96 + s * 3 + 0] = sd[base + 0];
        sd_cs[p * 96 + s * 3 + 1] = sd[base + 1];
        sd_cs[p * 96 + s * 3 + 2] = sd[base + 2];
    }
    __syncthreads();

    int lane = threadIdx.x, y = threadIdx.y;
    float acc[24];
    #pragma unroll
    for (int t = 0; t < 24; t++) acc[t] = 0.f;

    for (int p = 0; p < 100; p++) {
        float s0 = sd_cs[p * 96 + lane * 3 + 0];
        float s1 = sd_cs[p * 96 + lane * 3 + 1];
        float s2 = sd_cs[p * 96 + lane * 3 + 2];
        #pragma unroll
        for (int bb = 0; bb < 8; bb++) {
            float bp = beta_s[(y * 8 + bb) * 100 + p];
            acc[bb * 3 + 0] = fmaf(bp, s0, acc[bb * 3 + 0]);
            acc[bb * 3 + 1] = fmaf(bp, s1, acc[bb * 3 + 1]);
            acc[bb * 3 + 2] = fmaf(bp, s2, acc[bb * 3 + 2]);
        }
    }
    int myidx = idxs[lane];
    float v0 = vt[3 * myidx + 0], v1 = vt[3 * myidx + 1], v2 = vt[3 * myidx + 2];
    #pragma unroll
    for (int bb = 0; bb < 8; bb++) {
        acc[bb * 3 + 0] += v0; acc[bb * 3 + 1] += v1; acc[bb * 3 + 2] += v2;
    }
    float mx[24];
    #pragma unroll
    for (int t = 0; t < 24; t++) mx[t] = acc[t];

    for (int off = 16; off; off >>= 1) {
        #pragma unroll
        for (int t = 0; t < 24; t++) {
            float om = __shfl_xor_sync(0xffffffffu, acc[t], off);
            float ox = __shfl_xor_sync(0xffffffffu, mx[t],  off);
            acc[t] = fminf(acc[t], om);
            mx[t]  = fmaxf(mx[t],  ox);
        }
    }
    if (lane < 8) {
        int b = y * 8 + lane;
        float* dst = g_part + ((size_t)(j * 4 + ch) * 64 + b) * 6;
        dst[0] = acc[lane * 3 + 0]; dst[1] = acc[lane * 3 + 1]; dst[2] = acc[lane * 3 + 2];
        dst[3] = mx[lane * 3 + 0];  dst[4] = mx[lane * 3 + 1];  dst[5] = mx[lane * 3 + 2];
    }
}

// ---------------- Kernel A2: chunk-reduce + Rodrigues + kinematic chain -> G1 ----
__global__ void k_chain(const float* __restrict__ pose)
{
    int b = blockIdx.x, t = threadIdx.x;
    __shared__ float R[24][9], Jl[24][3], Gr[24][9], Gt[24][3];

    if (t < 24) {
        if (t == 0) {
            Jl[0][0] = 0.f; Jl[0][1] = 0.f; Jl[0][2] = 0.f;
        } else {
            int j = t - 1;
            float mn0 = 3.4e38f, mn1 = 3.4e38f, mn2 = 3.4e38f;
            float mx0 = -3.4e38f, mx1 = -3.4e38f, mx2 = -3.4e38f;
            #pragma unroll
            for (int ch = 0; ch < 4; ch++) {
                const float* s = g_part + ((size_t)(j * 4 + ch) * 64 + b) * 6;
                mn0 = fminf(mn0, s[0]); mn1 = fminf(mn1, s[1]); mn2 = fminf(mn2, s[2]);
                mx0 = fmaxf(mx0, s[3]); mx1 = fmaxf(mx1, s[4]); mx2 = fmaxf(mx2, s[5]);
            }
            Jl[t][0] = 0.5f * (mn0 + mx0);
            Jl[t][1] = 0.5f * (mn1 + mx1);
            Jl[t][2] = 0.5f * (mn2 + mx2);
        }

        float rx = pose[b * 72 + t * 3 + 0];
        float ry = pose[b * 72 + t * 3 + 1];
        float rz = pose[b * 72 + t * 3 + 2];
        float th = sqrtf(rx * rx + ry * ry + rz * rz);
        th = fmaxf(th, 1e-6f);
        float s, c;
        sincosf(th, &s, &c);
        float inv = 1.0f / th;
        float x = rx * inv, y = ry * inv, z = rz * inv;
        float omc = 1.0f - c;
        R[t][0] = c + omc * x * x;     R[t][1] = omc * x * y - s * z; R[t][2] = omc * x * z + s * y;
        R[t][3] = omc * x * y + s * z; R[t][4] = c + omc * y * y;     R[t][5] = omc * y * z - s * x;
        R[t][6] = omc * x * z - s * y; R[t][7] = omc * y * z + s * x; R[t][8] = c + omc * z * z;
    }
    __syncthreads();

    if (t == 0) {
        for (int q = 0; q < 9; q++) Gr[0][q] = R[0][q];
        Gt[0][0] = Jl[0][0]; Gt[0][1] = Jl[0][1]; Gt[0][2] = Jl[0][2];
        for (int i = 1; i < 24; i++) {
            int p = (i - 1) >> 1;
            for (int r = 0; r < 3; r++)
                for (int cc = 0; cc < 3; cc++)
                    Gr[i][r * 3 + cc] = Gr[p][r * 3 + 0] * R[i][0 + cc]
                                      + Gr[p][r * 3 + 1] * R[i][3 + cc]
                                      + Gr[p][r * 3 + 2] * R[i][6 + cc];
            float dx = Jl[i][0] - Jl[p][0];
            float dy = Jl[i][1] - Jl[p][1];
            float dz = Jl[i][2] - Jl[p][2];
            for (int r = 0; r < 3; r++)
                Gt[i][r] = Gr[p][r * 3 + 0] * dx + Gr[p][r * 3 + 1] * dy
                         + Gr[p][r * 3 + 2] * dz + Gt[p][r];
        }
    }
    __syncthreads();

    if (t < 24) {
        float* d = g_G1 + ((size_t)b * 24 + t) * 12;
        for (int r = 0; r < 3; r++) {
            float tc = Gr[t][r * 3 + 0] * Jl[t][0] + Gr[t][r * 3 + 1] * Jl[t][1]
                     + Gr[t][r * 3 + 2] * Jl[t][2];
            d[r * 4 + 0] = Gr[t][r * 3 + 0];
            d[r * 4 + 1] = Gr[t][r * 3 + 1];
            d[r * 4 + 2] = Gr[t][r * 3 + 2];
            d[r * 4 + 3] = Gt[t][r] - tc;
        }
    }
}

// ---------------- Kernel B: tf32 blend + lane=vertex skinning + fused skeleton --
// grid (1250, 2), block (32 vertex-lanes, 16) = 512 threads, 2 batches/thread.
#define SM_G1    0
#define SM_W     9216
#define SM_BETA  (SM_W + 768)            // 9984
#define SM_SD    (SM_BETA + 32 * 132)    // 14208
#define SM_TOT   (SM_SD + 104 * 104)     // 25024 floats = 100096 B

__global__ __launch_bounds__(512, 2) void k_main(
    const float* __restrict__ beta, const float* __restrict__ trans,
    const float* __restrict__ sd, const float* __restrict__ vt,
    const float* __restrict__ wts,
    const int* __restrict__ joint_idx, const int* __restrict__ add_idx,
    float* __restrict__ out)
{
    extern __shared__ float sm[];
    float* g1_s   = sm + SM_G1;     // [24][32][12]
    float* w_s    = sm + SM_W;      // [24][32 verts]
    float* beta_s = sm + SM_BETA;   // [32][132] tf32
    float* sd_s   = sm + SM_SD;     // [104][104]; later aliased as vp[32][100]

    int tid = threadIdx.y * 32 + threadIdx.x;
    int n0 = blockIdx.x * 32;
    int b0 = blockIdx.y * 32;

    uint32_t sd_sm_u32 = (uint32_t)__cvta_generic_to_shared(sd_s);

    // ---- stage sd tile [100 rows][96 cols], pitch 104 ----
    {
        const float* base = sd + 3 * n0;
        for (int i = tid; i < 2400; i += 512) {
            int row = i / 24, q = i - row * 24;
            cp16(sd_sm_u32 + (uint32_t)(row * 416 + q * 16),
                 base + (size_t)row * 120000 + q * 4);
        }
        cp_commit();
    }
    for (int i = tid; i < 96; i += 512) {
        int r = 100 + i / 24, q = i - (i / 24) * 24;
        ((float4*)sd_s)[r * 26 + q] = make_float4(0.f, 0.f, 0.f, 0.f);
    }

    // ---- stage beta tf32 [32][132], K pad 100->104 ----
    for (int i = tid; i < 3328; i += 512) {
        int m = i / 104, k = i - m * 104;
        float v = (k < 100) ? beta[(size_t)(b0 + m) * 100 + k] : 0.f;
        beta_s[m * 132 + k] = __uint_as_float(f2tf32(v));
    }

    // ---- stage G1 (natural layout; skinning reads are warp-uniform) + weights ----
    for (int i = tid; i < 2304; i += 512) {
        int bb = i / 72, r = i - bb * 72;
        int k = r / 3, j4 = r - k * 3;
        ((float4*)g1_s)[(k * 32 + bb) * 3 + j4] =
            *(const float4*)(g_G1 + (size_t)(b0 + bb) * 288 + r * 4);
    }
    for (int i = tid; i < 768; i += 512) {
        int k = i >> 5, vl = i & 31;
        w_s[k * 32 + vl] = wts[(size_t)(n0 + vl) * 24 + k];
    }

    cp_wait<0>();
    __syncthreads();

    // ---- tf32 mma blend: 24 tile-tasks (mtile 0..1 x ntile 0..11) over 16 warps ----
    int wid  = threadIdx.y;
    int lane = threadIdx.x;
    int gid  = lane >> 2, tig = lane & 3;

    float c0[4] = {0.f, 0.f, 0.f, 0.f};
    float c1[4] = {0.f, 0.f, 0.f, 0.f};
    {
        int t0 = wid;                 // task for all 16 warps
        int mt = t0 / 12, nt = t0 % 12;
        const float* ap = beta_s + (mt * 16 + gid) * 132 + tig;
        const float* bp = sd_s + tig * 104 + nt * 8 + gid;
        #pragma unroll
        for (int ks = 0; ks < 13; ks++) {
            int ko = ks * 8;
            uint32_t a0 = __float_as_uint(ap[ko]);
            uint32_t a1 = __float_as_uint(ap[ko + 8 * 132]);
            uint32_t a2 = __float_as_uint(ap[ko + 4]);
            uint32_t a3 = __float_as_uint(ap[ko + 4 + 8 * 132]);
            const float* bk = bp + ko * 104;
            mma_tf32(c0, a0, a1, a2, a3,
                     __float_as_uint(bk[0]), __float_as_uint(bk[4 * 104]));
        }
        if (wid < 8) {
            int t1 = 16 + wid;        // second task for warps 0..7
            int mt1 = t1 / 12, nt1 = t1 % 12;
            const float* ap1 = beta_s + (mt1 * 16 + gid) * 132 + tig;
            const float* bp1 = sd_s + tig * 104 + nt1 * 8 + gid;
            #pragma unroll
            for (int ks = 0; ks < 13; ks++) {
                int ko = ks * 8;
                uint32_t a0 = __float_as_uint(ap1[ko]);
                uint32_t a1 = __float_as_uint(ap1[ko + 8 * 132]);
                uint32_t a2 = __float_as_uint(ap1[ko + 4]);
                uint32_t a3 = __float_as_uint(ap1[ko + 4 + 8 * 132]);
                const float* bk = bp1 + ko * 104;
                mma_tf32(c1, a0, a1, a2, a3,
                         __float_as_uint(bk[0]), __float_as_uint(bk[4 * 104]));
            }
        }
    }
    __syncthreads();   // all sd reads complete; safe to alias as vp

    // ---- redistribute D -> vp[batch][pitch 100] ----
    {
        float* vp = sd_s;
        int t0 = wid, mt = t0 / 12, nt = t0 % 12;
        int mrow = mt * 16 + gid, ncol = nt * 8 + 2 * tig;
        *(float2*)(vp + mrow * 100 + ncol)       = make_float2(c0[0], c0[1]);
        *(float2*)(vp + (mrow + 8) * 100 + ncol) = make_float2(c0[2], c0[3]);
        if (wid < 8) {
            int t1 = 16 + wid, mt1 = t1 / 12, nt1 = t1 % 12;
            int mrow1 = mt1 * 16 + gid, ncol1 = nt1 * 8 + 2 * tig;
            *(float2*)(vp + mrow1 * 100 + ncol1)       = make_float2(c1[0], c1[1]);
            *(float2*)(vp + (mrow1 + 8) * 100 + ncol1) = make_float2(c1[2], c1[3]);
        }
    }
    __syncthreads();

    // ---- skinning: lane = vertex, thread handles 2 batches ----
    {
        int v = threadIdx.x;
        int bl0 = threadIdx.y * 2, bl1 = bl0 + 1;
        const float* vp = sd_s;

        float vt0 = vt[(size_t)(n0 + v) * 3 + 0];
        float vt1 = vt[(size_t)(n0 + v) * 3 + 1];
        float vt2 = vt[(size_t)(n0 + v) * 3 + 2];

        float ax = vp[bl0 * 100 + v * 3 + 0] + vt0;
        float ay = vp[bl0 * 100 + v * 3 + 1] + vt1;
        float az = vp[bl0 * 100 + v * 3 + 2] + vt2;
        float bx = vp[bl1 * 100 + v * 3 + 0] + vt0;
        float by = vp[bl1 * 100 + v * 3 + 1] + vt1;
        float bz = vp[bl1 * 100 + v * 3 + 2] + vt2;

        float oa0 = trans[(b0 + bl0) * 3 + 0];
        float oa1 = trans[(b0 + bl0) * 3 + 1];
        float oa2 = trans[(b0 + bl0) * 3 + 2];
        float ob0 = trans[(b0 + bl1) * 3 + 0];
        float ob1 = trans[(b0 + bl1) * 3 + 1];
        float ob2 = trans[(b0 + bl1) * 3 + 2];

        #pragma unroll 4
        for (int k = 0; k < 24; k++) {
            float wv = w_s[k * 32 + v];
            const float4* gA = (const float4*)(g1_s + (k * 32 + bl0) * 12);
            float4 A0 = gA[0], A1 = gA[1], A2 = gA[2];
            const float4* gB = (const float4*)(g1_s + (k * 32 + bl1) * 12);
            float4 B0 = gB[0], B1 = gB[1], B2 = gB[2];

            float t0 = fmaf(A0.x, ax, fmaf(A0.y, ay, fmaf(A0.z, az, A0.w)));
            float t1 = fmaf(A1.x, ax, fmaf(A1.y, ay, fmaf(A1.z, az, A1.w)));
            float t2 = fmaf(A2.x, ax, fmaf(A2.y, ay, fmaf(A2.z, az, A2.w)));
            oa0 = fmaf(wv, t0, oa0);
            oa1 = fmaf(wv, t1, oa1);
            oa2 = fmaf(wv, t2, oa2);

            float s0 = fmaf(B0.x, bx, fmaf(B0.y, by, fmaf(B0.z, bz, B0.w)));
            float s1 = fmaf(B1.x, bx, fmaf(B1.y, by, fmaf(B1.z, bz, B1.w)));
            float s2 = fmaf(B2.x, bx, fmaf(B2.y, by, fmaf(B2.z, bz, B2.w)));
            ob0 = fmaf(wv, s0, ob0);
            ob1 = fmaf(wv, s1, ob1);
            ob2 = fmaf(wv, s2, ob2);
        }

        float* dA = out + ((size_t)(b0 + bl0) * 40000 + n0 + v) * 3;
        dA[0] = oa0; dA[1] = oa1; dA[2] = oa2;
        float* dB = out + ((size_t)(b0 + bl1) * 40000 + n0 + v) * 3;
        dB[0] = ob0; dB[1] = ob1; dB[2] = ob2;
    }

    // ---- fused skeleton: last NROW blocks finalize one row each ----
    __threadfence();
    __syncthreads();
    __shared__ int ticket;
    if (tid == 0) ticket = atomicAdd(&g_done, 1);
    __syncthreads();
    int tk = ticket;
    if (tk >= NBLK - NROW) {
        if (tid == 0) {
            while (atomicAdd(&g_done, 0) < NBLK) __nanosleep(64);
        }
        __syncthreads();
        __threadfence();   // acquire: all blocks' out-writes visible

        int row = tk - (NBLK - NROW);
        const int* idxrow = (row < 23) ? (joint_idx + row * 128)
                                       : (add_idx + (row - 23) * 128);
        int tb = tid & 63;      // batch 0..63
        int chunk = tid >> 6;   // 0..7, 16 verts each
        float mn0 = 3.4e38f, mn1 = 3.4e38f, mn2 = 3.4e38f;
        float mx0 = -3.4e38f, mx1 = -3.4e38f, mx2 = -3.4e38f;
        for (int i = 0; i < 16; i++) {
            int v = idxrow[chunk * 16 + i];
            const float* p = out + ((size_t)tb * 40000 + v) * 3;
            float x = p[0], y = p[1], z = p[2];
            mn0 = fminf(mn0, x); mx0 = fmaxf(mx0, x);
            mn1 = fminf(mn1, y); mx1 = fmaxf(mx1, y);
            mn2 = fminf(mn2, z); mx2 = fmaxf(mx2, z);
        }
        float* red = sm;   // reuse dynamic smem: [8][64][6]
        float* rr = red + (chunk * 64 + tb) * 6;
        rr[0] = mn0; rr[1] = mn1; rr[2] = mn2;
        rr[3] = mx0; rr[4] = mx1; rr[5] = mx2;
        __syncthreads();
        if (chunk == 0) {
            #pragma unroll
            for (int c = 1; c < 8; c++) {
                const float* s = red + (c * 64 + tb) * 6;
                mn0 = fminf(mn0, s[0]); mn1 = fminf(mn1, s[1]); mn2 = fminf(mn2, s[2]);
                mx0 = fmaxf(mx0, s[3]); mx1 = fmaxf(mx1, s[4]); mx2 = fmaxf(mx2, s[5]);
            }
            int orow = (row < 23) ? (1 + row) : (24 + (row - 23));
            float* s = out + SKEL_OFF + ((size_t)tb * 31 + orow) * 3;
            s[0] = 0.5f * (mn0 + mx0);
            s[1] = 0.5f * (mn1 + mx1);
            s[2] = 0.5f * (mn2 + mx2);
            if (row == 0) {
                float* z0 = out + SKEL_OFF + (size_t)tb * 31 * 3;
                z0[0] = 0.f; z0[1] = 0.f; z0[2] = 0.f;
            }
        }
        __syncthreads();
        if (tid == 0) {
            int d = atomicAdd(&g_done2, 1);
            if (d == NROW - 1) {           // last finalizer resets for replay
                atomicExch(&g_done, 0);
                atomicExch(&g_done2, 0);
            }
        }
    }
}

// ---------------- launch ----------------
extern "C" void kernel_launch(void* const* d_in, const int* in_sizes, int n_in,
                              void* d_out, int out_size)
{
    const float* beta      = (const float*)d_in[0];
    const float* pose      = (const float*)d_in[1];
    const float* trans     = (const float*)d_in[2];
    const float* sd        = (const float*)d_in[3];
    const float* vt        = (const float*)d_in[4];
    const float* wts       = (const float*)d_in[5];
    const int*   joint_idx = (const int*)d_in[8];
    const int*   add_idx   = (const int*)d_in[9];
    float* out = (float*)d_out;

    cudaFuncSetAttribute(k_joint_gather, cudaFuncAttributeMaxDynamicSharedMemorySize, 64000);
    cudaFuncSetAttribute(k_main,         cudaFuncAttributeMaxDynamicSharedMemorySize, SM_TOT * 4);

    k_joint_gather<<<dim3(23, 4), dim3(32, 8), 64000>>>(beta, sd, vt, joint_idx);
    k_chain<<<64, 32>>>(pose);
    k_main<<<dim3(1250, 2), dim3(32, 16), SM_TOT * 4>>>(beta, trans, sd, vt, wts,
                                                        joint_idx, add_idx, out);
}

// round 15
// speedup vs baseline: 1.2527x; 1.2527x over previous
#include <cuda_runtime.h>
#include <math.h>
#include <stdint.h>

#define B_   64
#define NV   40000
#define P_   100
#define NJ   24
#define SKEL_OFF 7680000   // 64*40000*3

// ---------------- scratch (device globals; no allocation allowed) ----------------
__device__ float g_G1[B_ * NJ * 12];
__device__ float g_part[23 * 4 * B_ * 6];
__device__ float g_spart[30 * 8 * B_ * 6];
__device__ int   g_cnt[30];   // zero-initialized; returns to 0 after each replay

// ---------------- cp.async helpers ----------------
__device__ __forceinline__ void cp16(uint32_t dst, const void* src) {
    asm volatile("cp.async.cg.shared.global [%0], [%1], 16;" :: "r"(dst), "l"(src));
}
__device__ __forceinline__ void cp_commit() {
    asm volatile("cp.async.commit_group;");
}
template <int N>
__device__ __forceinline__ void cp_wait() {
    asm volatile("cp.async.wait_group %0;" :: "n"(N));
}

// ---------------- tf32 mma helpers ----------------
__device__ __forceinline__ uint32_t f2tf32(float f) {
    uint32_t u; asm("cvt.rna.tf32.f32 %0, %1;" : "=r"(u) : "f"(f)); return u;
}
__device__ __forceinline__ void mma_tf32(float c[4],
    uint32_t a0, uint32_t a1, uint32_t a2, uint32_t a3,
    uint32_t b0, uint32_t b1)
{
    asm volatile(
        "mma.sync.aligned.m16n8k8.row.col.f32.tf32.tf32.f32 "
        "{%0,%1,%2,%3},{%4,%5,%6,%7},{%8,%9},{%0,%1,%2,%3};"
        : "+f"(c[0]), "+f"(c[1]), "+f"(c[2]), "+f"(c[3])
        : "r"(a0), "r"(a1), "r"(a2), "r"(a3), "r"(b0), "r"(b1));
}

// ---------------- Kernel A1: gathered v_posed + per-chunk min/max ----------------
// grid (23 joints, 4 chunks, 2 batch-halves), block (32 idx-lanes, 8) = 256 threads
// Each thread: 4 batches x 3 comps over K=100.
__global__ __launch_bounds__(256) void k_joint_gather(
    const float* __restrict__ beta, const float* __restrict__ sd,
    const float* __restrict__ vt, const int* __restrict__ joint_idx)
{
    extern __shared__ float sm[];
    float* beta_s = sm;          // [32][100] for this batch half
    float* sd_cs  = sm + 3200;   // [100][96]
    __shared__ int idxs[32];

    int j = blockIdx.x, ch = blockIdx.y, bh = blockIdx.z;
    int tid = threadIdx.y * 32 + threadIdx.x;

    if (tid < 32) idxs[tid] = joint_idx[j * 128 + ch * 32 + tid];
    for (int i = tid; i < 3200; i += 256) beta_s[i] = beta[(size_t)bh * 3200 + i];
    __syncthreads();

    for (int i = tid; i < 3200; i += 256) {
        int p = i >> 5, s = i & 31;
        size_t base = (size_t)p * 120000 + 3 * idxs[s];
        sd_cs[p * 96 + s * 3 + 0] = sd[base + 0];
        sd_cs[p * 96 + s * 3 + 1] = sd[base + 1];
        sd_cs[p * 96 + s * 3 + 2] = sd[base + 2];
    }
    __syncthreads();

    int lane = threadIdx.x, y = threadIdx.y;
    float acc[12];
    #pragma unroll
    for (int t = 0; t < 12; t++) acc[t] = 0.f;

    for (int p = 0; p < 100; p++) {
        float s0 = sd_cs[p * 96 + lane * 3 + 0];
        float s1 = sd_cs[p * 96 + lane * 3 + 1];
        float s2 = sd_cs[p * 96 + lane * 3 + 2];
        #pragma unroll
        for (int bb = 0; bb < 4; bb++) {
            float bp = beta_s[(y * 4 + bb) * 100 + p];
            acc[bb * 3 + 0] = fmaf(bp, s0, acc[bb * 3 + 0]);
            acc[bb * 3 + 1] = fmaf(bp, s1, acc[bb * 3 + 1]);
            acc[bb * 3 + 2] = fmaf(bp, s2, acc[bb * 3 + 2]);
        }
    }
    int myidx = idxs[lane];
    float v0 = vt[3 * myidx + 0], v1 = vt[3 * myidx + 1], v2 = vt[3 * myidx + 2];
    #pragma unroll
    for (int bb = 0; bb < 4; bb++) {
        acc[bb * 3 + 0] += v0; acc[bb * 3 + 1] += v1; acc[bb * 3 + 2] += v2;
    }
    float mx[12];
    #pragma unroll
    for (int t = 0; t < 12; t++) mx[t] = acc[t];

    // butterfly min/max across the 32 gathered vertices
    for (int off = 16; off; off >>= 1) {
        #pragma unroll
        for (int t = 0; t < 12; t++) {
            float om = __shfl_xor_sync(0xffffffffu, acc[t], off);
            float ox = __shfl_xor_sync(0xffffffffu, mx[t],  off);
            acc[t] = fminf(acc[t], om);
            mx[t]  = fmaxf(mx[t],  ox);
        }
    }
    if (lane < 4) {
        int b = bh * 32 + y * 4 + lane;
        float* dst = g_part + ((size_t)(j * 4 + ch) * 64 + b) * 6;
        dst[0] = acc[lane * 3 + 0]; dst[1] = acc[lane * 3 + 1]; dst[2] = acc[lane * 3 + 2];
        dst[3] = mx[lane * 3 + 0];  dst[4] = mx[lane * 3 + 1];  dst[5] = mx[lane * 3 + 2];
    }
}

// ---------------- Kernel A2: chunk-reduce + Rodrigues + kinematic chain -> G1 ----
__global__ void k_chain(const float* __restrict__ pose)
{
    int b = blockIdx.x, t = threadIdx.x;
    __shared__ float R[24][9], Jl[24][3], Gr[24][9], Gt[24][3];

    if (t < 24) {
        if (t == 0) {
            Jl[0][0] = 0.f; Jl[0][1] = 0.f; Jl[0][2] = 0.f;
        } else {
            int j = t - 1;
            float mn0 = 3.4e38f, mn1 = 3.4e38f, mn2 = 3.4e38f;
            float mx0 = -3.4e38f, mx1 = -3.4e38f, mx2 = -3.4e38f;
            #pragma unroll
            for (int ch = 0; ch < 4; ch++) {
                const float* s = g_part + ((size_t)(j * 4 + ch) * 64 + b) * 6;
                mn0 = fminf(mn0, s[0]); mn1 = fminf(mn1, s[1]); mn2 = fminf(mn2, s[2]);
                mx0 = fmaxf(mx0, s[3]); mx1 = fmaxf(mx1, s[4]); mx2 = fmaxf(mx2, s[5]);
            }
            Jl[t][0] = 0.5f * (mn0 + mx0);
            Jl[t][1] = 0.5f * (mn1 + mx1);
            Jl[t][2] = 0.5f * (mn2 + mx2);
        }

        float rx = pose[b * 72 + t * 3 + 0];
        float ry = pose[b * 72 + t * 3 + 1];
        float rz = pose[b * 72 + t * 3 + 2];
        float th = sqrtf(rx * rx + ry * ry + rz * rz);
        th = fmaxf(th, 1e-6f);
        float s, c;
        sincosf(th, &s, &c);
        float inv = 1.0f / th;
        float x = rx * inv, y = ry * inv, z = rz * inv;
        float omc = 1.0f - c;
        R[t][0] = c + omc * x * x;     R[t][1] = omc * x * y - s * z; R[t][2] = omc * x * z + s * y;
        R[t][3] = omc * x * y + s * z; R[t][4] = c + omc * y * y;     R[t][5] = omc * y * z - s * x;
        R[t][6] = omc * x * z - s * y; R[t][7] = omc * y * z + s * x; R[t][8] = c + omc * z * z;
    }
    __syncthreads();

    if (t == 0) {
        for (int q = 0; q < 9; q++) Gr[0][q] = R[0][q];
        Gt[0][0] = Jl[0][0]; Gt[0][1] = Jl[0][1]; Gt[0][2] = Jl[0][2];
        for (int i = 1; i < 24; i++) {
            int p = (i - 1) >> 1;
            for (int r = 0; r < 3; r++)
                for (int cc = 0; cc < 3; cc++)
                    Gr[i][r * 3 + cc] = Gr[p][r * 3 + 0] * R[i][0 + cc]
                                      + Gr[p][r * 3 + 1] * R[i][3 + cc]
                                      + Gr[p][r * 3 + 2] * R[i][6 + cc];
            float dx = Jl[i][0] - Jl[p][0];
            float dy = Jl[i][1] - Jl[p][1];
            float dz = Jl[i][2] - Jl[p][2];
            for (int r = 0; r < 3; r++)
                Gt[i][r] = Gr[p][r * 3 + 0] * dx + Gr[p][r * 3 + 1] * dy
                         + Gr[p][r * 3 + 2] * dz + Gt[p][r];
        }
    }
    __syncthreads();

    if (t < 24) {
        float* d = g_G1 + ((size_t)b * 24 + t) * 12;
        for (int r = 0; r < 3; r++) {
            float tc = Gr[t][r * 3 + 0] * Jl[t][0] + Gr[t][r * 3 + 1] * Jl[t][1]
                     + Gr[t][r * 3 + 2] * Jl[t][2];
            d[r * 4 + 0] = Gr[t][r * 3 + 0];
            d[r * 4 + 1] = Gr[t][r * 3 + 1];
            d[r * 4 + 2] = Gr[t][r * 3 + 2];
            d[r * 4 + 3] = Gt[t][r] - tc;
        }
    }
}

// ---------------- Kernel B: tf32-mma shape blend + fp32 skinning (R10) ----------
// grid (1250, 2), block (32, 8) = 256 threads (8 warps), 4 vertices/thread.
#define SM_G1    0
#define SM_W     9216
#define SM_BETA  (SM_W + 768)            // 9984
#define SM_SD    (SM_BETA + 32 * 132)    // 14208
#define SM_TOT   (SM_SD + 104 * 104)     // 25024 floats = 100096 B

__global__ __launch_bounds__(256, 2) void k_main(
    const float* __restrict__ beta, const float* __restrict__ trans,
    const float* __restrict__ sd, const float* __restrict__ vt,
    const float* __restrict__ wts, float* __restrict__ out)
{
    extern __shared__ float sm[];
    float* g1_s   = sm + SM_G1;
    float* w_s    = sm + SM_W;
    float* beta_s = sm + SM_BETA;
    float* sd_s   = sm + SM_SD;

    int tid = threadIdx.y * 32 + threadIdx.x;
    int n0 = blockIdx.x * 32;
    int b0 = blockIdx.y * 32;

    uint32_t sd_sm_u32 = (uint32_t)__cvta_generic_to_shared(sd_s);

    // ---- stage sd tile [100 rows][96 cols] via cp.async, pitch 104 ----
    {
        const float* base = sd + 3 * n0;
        for (int i = tid; i < 2400; i += 256) {
            int row = i / 24, q = i - row * 24;
            cp16(sd_sm_u32 + (uint32_t)(row * 416 + q * 16),
                 base + (size_t)row * 120000 + q * 4);
        }
        cp_commit();
    }
    // zero K-pad rows 100..103
    for (int i = tid; i < 96; i += 256) {
        int r = 100 + i / 24, q = i - (i / 24) * 24;
        ((float4*)sd_s)[r * 26 + q] = make_float4(0.f, 0.f, 0.f, 0.f);
    }

    // ---- stage beta tf32 [32][132], K pad 100->104 ----
    for (int i = tid; i < 3328; i += 256) {
        int m = i / 104, k = i - m * 104;
        float v = (k < 100) ? beta[(size_t)(b0 + m) * 100 + k] : 0.f;
        beta_s[m * 132 + k] = __uint_as_float(f2tf32(v));
    }

    // ---- stage G1 + weights ----
    for (int i = tid; i < 2304; i += 256) {
        int bb = i / 72, r = i - bb * 72;
        int k = r / 3, j4 = r - k * 3;
        ((float4*)g1_s)[(k * 32 + bb) * 3 + j4] =
            *(const float4*)(g_G1 + (size_t)(b0 + bb) * 288 + r * 4);
    }
    for (int i = tid; i < 768; i += 256) {
        int k = i >> 5, vl = i & 31;
        w_s[k * 32 + vl] = wts[(size_t)(n0 + vl) * 24 + k];
    }

    cp_wait<0>();
    __syncthreads();

    // ---- tf32 mma blend: warp w -> mtile = w>>2, ntiles {3*(w&3) .. +2} ----
    int wid  = threadIdx.y;
    int lane = threadIdx.x;
    int gid  = lane >> 2, tig = lane & 3;
    int mtile = wid >> 2;
    int ntile0 = (wid & 3) * 3;

    float c[3][4];
    #pragma unroll
    for (int t = 0; t < 3; t++)
        #pragma unroll
        for (int q = 0; q < 4; q++) c[t][q] = 0.f;

    const float* ap = beta_s + (mtile * 16 + gid) * 132 + tig;
    const float* bp = sd_s + tig * 104 + ntile0 * 8 + gid;

    #pragma unroll
    for (int ks = 0; ks < 13; ks++) {
        int ko = ks * 8;
        uint32_t a0 = __float_as_uint(ap[ko]);
        uint32_t a1 = __float_as_uint(ap[ko + 8 * 132]);
        uint32_t a2 = __float_as_uint(ap[ko + 4]);
        uint32_t a3 = __float_as_uint(ap[ko + 4 + 8 * 132]);
        const float* bk = bp + ko * 104;
        uint32_t b00 = __float_as_uint(bk[0]);
        uint32_t b01 = __float_as_uint(bk[4 * 104]);
        uint32_t b10 = __float_as_uint(bk[8]);
        uint32_t b11 = __float_as_uint(bk[8 + 4 * 104]);
        uint32_t b20 = __float_as_uint(bk[16]);
        uint32_t b21 = __float_as_uint(bk[16 + 4 * 104]);
        mma_tf32(c[0], a0, a1, a2, a3, b00, b01);
        mma_tf32(c[1], a0, a1, a2, a3, b10, b11);
        mma_tf32(c[2], a0, a1, a2, a3, b20, b21);
    }

    __syncthreads();   // all sd reads done; safe to overwrite with vp

    // ---- redistribute D -> vp[m=batch][pitch 100] ----
    {
        float* vp = sd_s;
        int mrow = mtile * 16 + gid;
        #pragma unroll
        for (int t = 0; t < 3; t++) {
            int ncol = (ntile0 + t) * 8 + 2 * tig;
            *(float2*)(vp + mrow * 100 + ncol)       = make_float2(c[t][0], c[t][1]);
            *(float2*)(vp + (mrow + 8) * 100 + ncol) = make_float2(c[t][2], c[t][3]);
        }
    }
    __syncthreads();

    // ---- epilogue: acc = vp + vt, then fp32 skinning ----
    int b = threadIdx.x, vl0 = threadIdx.y * 4;

    float acc[12];
    {
        const float4* vprow = (const float4*)(sd_s + b * 100 + vl0 * 3);
        const float4* v4 = (const float4*)(vt + (size_t)(n0 + vl0) * 3);
        float4 p0 = vprow[0], p1 = vprow[1], p2 = vprow[2];
        float4 a = v4[0], b4 = v4[1], c4 = v4[2];
        acc[0] = p0.x + a.x;  acc[1] = p0.y + a.y;  acc[2]  = p0.z + a.z;  acc[3]  = p0.w + a.w;
        acc[4] = p1.x + b4.x; acc[5] = p1.y + b4.y; acc[6]  = p1.z + b4.z; acc[7]  = p1.w + b4.w;
        acc[8] = p2.x + c4.x; acc[9] = p2.y + c4.y; acc[10] = p2.z + c4.z; acc[11] = p2.w + c4.w;
    }

    float tr0 = trans[(b0 + b) * 3 + 0];
    float tr1 = trans[(b0 + b) * 3 + 1];
    float tr2 = trans[(b0 + b) * 3 + 2];
    float o[12] = {tr0, tr1, tr2, tr0, tr1, tr2, tr0, tr1, tr2, tr0, tr1, tr2};

    #pragma unroll 4
    for (int k = 0; k < 24; k++) {
        const float4* g = (const float4*)(g1_s + (k * 32 + b) * 12);
        float4 g0 = g[0], g1v = g[1], g2 = g[2];
        float4 w4 = *(const float4*)(w_s + k * 32 + vl0);
        float wv[4] = {w4.x, w4.y, w4.z, w4.w};
        #pragma unroll
        for (int vi = 0; vi < 4; vi++) {
            float vx = acc[vi * 3 + 0], vy = acc[vi * 3 + 1], vz = acc[vi * 3 + 2];
            float t0 = fmaf(g0.x,  vx, fmaf(g0.y,  vy, fmaf(g0.z,  vz, g0.w)));
            float t1 = fmaf(g1v.x, vx, fmaf(g1v.y, vy, fmaf(g1v.z, vz, g1v.w)));
            float t2 = fmaf(g2.x,  vx, fmaf(g2.y,  vy, fmaf(g2.z,  vz, g2.w)));
            o[vi * 3 + 0] = fmaf(wv[vi], t0, o[vi * 3 + 0]);
            o[vi * 3 + 1] = fmaf(wv[vi], t1, o[vi * 3 + 1]);
            o[vi * 3 + 2] = fmaf(wv[vi], t2, o[vi * 3 + 2]);
        }
    }

    float4* dst = (float4*)(out + ((size_t)(b0 + b) * 40000 + n0 + vl0) * 3);
    dst[0] = make_float4(o[0], o[1], o[2],  o[3]);
    dst[1] = make_float4(o[4], o[5], o[6],  o[7]);
    dst[2] = make_float4(o[8], o[9], o[10], o[11]);
}

// ---------------- Kernel C: skeleton partials + fused final reduction -----------
// grid (30, 8), block (64, 4); last-arriving block per row finalizes.
__global__ __launch_bounds__(256) void k_skel_part(
    const int* __restrict__ joint_idx, const int* __restrict__ add_idx,
    float* __restrict__ out)
{
    int j = blockIdx.x, ch = blockIdx.y;
    const int* row = (j < 23) ? (joint_idx + j * 128) : (add_idx + (j - 23) * 128);

    __shared__ int vs[16];
    __shared__ int ticket;
    int tid = threadIdx.y * 64 + threadIdx.x;
    if (tid < 16) vs[tid] = row[ch * 16 + tid];
    __syncthreads();

    int b = threadIdx.x, q = threadIdx.y;
    float mn0 = 3.4e38f, mn1 = 3.4e38f, mn2 = 3.4e38f;
    float mx0 = -3.4e38f, mx1 = -3.4e38f, mx2 = -3.4e38f;
    #pragma unroll
    for (int i = 0; i < 4; i++) {
        int v = vs[q * 4 + i];
        const float* p = out + ((size_t)b * 40000 + v) * 3;
        float x = p[0], y = p[1], z = p[2];
        mn0 = fminf(mn0, x); mx0 = fmaxf(mx0, x);
        mn1 = fminf(mn1, y); mx1 = fmaxf(mx1, y);
        mn2 = fminf(mn2, z); mx2 = fmaxf(mx2, z);
    }
    __shared__ float red[4][64][6];
    red[q][b][0] = mn0; red[q][b][1] = mn1; red[q][b][2] = mn2;
    red[q][b][3] = mx0; red[q][b][4] = mx1; red[q][b][5] = mx2;
    __syncthreads();
    if (q == 0) {
        #pragma unroll
        for (int c = 1; c < 4; c++) {
            mn0 = fminf(mn0, red[c][b][0]); mn1 = fminf(mn1, red[c][b][1]); mn2 = fminf(mn2, red[c][b][2]);
            mx0 = fmaxf(mx0, red[c][b][3]); mx1 = fmaxf(mx1, red[c][b][4]); mx2 = fmaxf(mx2, red[c][b][5]);
        }
        float* dst = g_spart + ((size_t)(j * 8 + ch) * 64 + b) * 6;
        dst[0] = mn0; dst[1] = mn1; dst[2] = mn2;
        dst[3] = mx0; dst[4] = mx1; dst[5] = mx2;
    }

    // threadfence-reduction handoff: last block of the 8 chunks finalizes row j
    __threadfence();
    __syncthreads();
    if (tid == 0) ticket = atomicAdd(&g_cnt[j], 1);
    __syncthreads();
    if (ticket == 7) {
        __threadfence();
        if (q == 0) {
            int orow = (j < 23) ? (1 + j) : (24 + (j - 23));
            float fn0 = 3.4e38f, fn1 = 3.4e38f, fn2 = 3.4e38f;
            float fx0 = -3.4e38f, fx1 = -3.4e38f, fx2 = -3.4e38f;
            #pragma unroll
            for (int c = 0; c < 8; c++) {
                const float* s = g_spart + ((size_t)(j * 8 + c) * 64 + b) * 6;
                fn0 = fminf(fn0, s[0]); fn1 = fminf(fn1, s[1]); fn2 = fminf(fn2, s[2]);
                fx0 = fmaxf(fx0, s[3]); fx1 = fmaxf(fx1, s[4]); fx2 = fmaxf(fx2, s[5]);
            }
            float* s = out + SKEL_OFF + ((size_t)b * 31 + orow) * 3;
            s[0] = 0.5f * (fn0 + fx0);
            s[1] = 0.5f * (fn1 + fx1);
            s[2] = 0.5f * (fn2 + fx2);
            if (j == 0) {
                float* z0 = out + SKEL_OFF + (size_t)b * 31 * 3;
                z0[0] = 0.f; z0[1] = 0.f; z0[2] = 0.f;
            }
        }
        if (tid == 0) atomicExch(&g_cnt[j], 0);   // reset for next graph replay
    }
}

// ---------------- launch ----------------
extern "C" void kernel_launch(void* const* d_in, const int* in_sizes, int n_in,
                              void* d_out, int out_size)
{
    const float* beta      = (const float*)d_in[0];
    const float* pose      = (const float*)d_in[1];
    const float* trans     = (const float*)d_in[2];
    const float* sd        = (const float*)d_in[3];
    const float* vt        = (const float*)d_in[4];
    const float* wts       = (const float*)d_in[5];
    const int*   joint_idx = (const int*)d_in[8];
    const int*   add_idx   = (const int*)d_in[9];
    float* out = (float*)d_out;

    cudaFuncSetAttribute(k_joint_gather, cudaFuncAttributeMaxDynamicSharedMemorySize, 51200);
    cudaFuncSetAttribute(k_main,         cudaFuncAttributeMaxDynamicSharedMemorySize, SM_TOT * 4);

    k_joint_gather<<<dim3(23, 4, 2), dim3(32, 8), 51200>>>(beta, sd, vt, joint_idx);
    k_chain<<<64, 32>>>(pose);
    k_main<<<dim3(1250, 2), dim3(32, 8), SM_TOT * 4>>>(beta, trans, sd, vt, wts, out);
    k_skel_part<<<dim3(30, 8), dim3(64, 4)>>>(joint_idx, add_idx, out);
}

// round 16
// speedup vs baseline: 1.3395x; 1.0693x over previous
#include <cuda_runtime.h>
#include <math.h>
#include <stdint.h>

#define B_   64
#define NV   40000
#define P_   100
#define NJ   24
#define SKEL_OFF 7680000   // 64*40000*3

// ---------------- scratch (device globals; no allocation allowed) ----------------
__device__ float g_G1[B_ * NJ * 12];
__device__ float g_part[23 * 4 * B_ * 6];
__device__ float g_spart[30 * 8 * B_ * 6];
__device__ int   g_cnt[30];   // zero-initialized; returns to 0 after each replay

// ---------------- cp.async helpers ----------------
__device__ __forceinline__ void cp16(uint32_t dst, const void* src) {
    asm volatile("cp.async.cg.shared.global [%0], [%1], 16;" :: "r"(dst), "l"(src));
}
__device__ __forceinline__ void cp_commit() {
    asm volatile("cp.async.commit_group;");
}
template <int N>
__device__ __forceinline__ void cp_wait() {
    asm volatile("cp.async.wait_group %0;" :: "n"(N));
}

// ---------------- tf32 mma helpers ----------------
__device__ __forceinline__ uint32_t f2tf32(float f) {
    uint32_t u; asm("cvt.rna.tf32.f32 %0, %1;" : "=r"(u) : "f"(f)); return u;
}
__device__ __forceinline__ void mma_tf32(float c[4],
    uint32_t a0, uint32_t a1, uint32_t a2, uint32_t a3,
    uint32_t b0, uint32_t b1)
{
    asm volatile(
        "mma.sync.aligned.m16n8k8.row.col.f32.tf32.tf32.f32 "
        "{%0,%1,%2,%3},{%4,%5,%6,%7},{%8,%9},{%0,%1,%2,%3};"
        : "+f"(c[0]), "+f"(c[1]), "+f"(c[2]), "+f"(c[3])
        : "r"(a0), "r"(a1), "r"(a2), "r"(a3), "r"(b0), "r"(b1));
}

// ---------------- Kernel A1: gathered v_posed + per-chunk min/max ----------------
// grid (23 joints, 4 chunks), block (32 idx-lanes, 16) = 512 threads.
// sd staged ONCE per block (no duplication); each thread: 4 batches x 3 comps.
__global__ __launch_bounds__(512) void k_joint_gather(
    const float* __restrict__ beta, const float* __restrict__ sd,
    const float* __restrict__ vt, const int* __restrict__ joint_idx)
{
    extern __shared__ float sm[];
    float* beta_s = sm;          // [64][100]
    float* sd_cs  = sm + 6400;   // [100][96]
    __shared__ int idxs[32];

    int j = blockIdx.x, ch = blockIdx.y;
    int tid = threadIdx.y * 32 + threadIdx.x;

    if (tid < 32) idxs[tid] = joint_idx[j * 128 + ch * 32 + tid];
    for (int i = tid; i < 6400; i += 512) beta_s[i] = beta[i];
    __syncthreads();

    for (int i = tid; i < 3200; i += 512) {
        int p = i >> 5, s = i & 31;
        size_t base = (size_t)p * 120000 + 3 * idxs[s];
        sd_cs[p * 96 + s * 3 + 0] = sd[base + 0];
        sd_cs[p * 96 + s * 3 + 1] = sd[base + 1];
        sd_cs[p * 96 + s * 3 + 2] = sd[base + 2];
    }
    __syncthreads();

    int lane = threadIdx.x, y = threadIdx.y;
    float acc[12];
    #pragma unroll
    for (int t = 0; t < 12; t++) acc[t] = 0.f;

    for (int p = 0; p < 100; p++) {
        float s0 = sd_cs[p * 96 + lane * 3 + 0];
        float s1 = sd_cs[p * 96 + lane * 3 + 1];
        float s2 = sd_cs[p * 96 + lane * 3 + 2];
        #pragma unroll
        for (int bb = 0; bb < 4; bb++) {
            float bp = beta_s[(y * 4 + bb) * 100 + p];
            acc[bb * 3 + 0] = fmaf(bp, s0, acc[bb * 3 + 0]);
            acc[bb * 3 + 1] = fmaf(bp, s1, acc[bb * 3 + 1]);
            acc[bb * 3 + 2] = fmaf(bp, s2, acc[bb * 3 + 2]);
        }
    }
    int myidx = idxs[lane];
    float v0 = vt[3 * myidx + 0], v1 = vt[3 * myidx + 1], v2 = vt[3 * myidx + 2];
    #pragma unroll
    for (int bb = 0; bb < 4; bb++) {
        acc[bb * 3 + 0] += v0; acc[bb * 3 + 1] += v1; acc[bb * 3 + 2] += v2;
    }
    float mx[12];
    #pragma unroll
    for (int t = 0; t < 12; t++) mx[t] = acc[t];

    // butterfly min/max across the 32 gathered vertices
    for (int off = 16; off; off >>= 1) {
        #pragma unroll
        for (int t = 0; t < 12; t++) {
            float om = __shfl_xor_sync(0xffffffffu, acc[t], off);
            float ox = __shfl_xor_sync(0xffffffffu, mx[t],  off);
            acc[t] = fminf(acc[t], om);
            mx[t]  = fmaxf(mx[t],  ox);
        }
    }
    if (lane < 4) {
        int b = y * 4 + lane;
        float* dst = g_part + ((size_t)(j * 4 + ch) * 64 + b) * 6;
        dst[0] = acc[lane * 3 + 0]; dst[1] = acc[lane * 3 + 1]; dst[2] = acc[lane * 3 + 2];
        dst[3] = mx[lane * 3 + 0];  dst[4] = mx[lane * 3 + 1];  dst[5] = mx[lane * 3 + 2];
    }
}

// ---------------- Kernel A2: chunk-reduce + Rodrigues + kinematic chain -> G1 ----
__global__ void k_chain(const float* __restrict__ pose)
{
    int b = blockIdx.x, t = threadIdx.x;
    __shared__ float R[24][9], Jl[24][3], Gr[24][9], Gt[24][3];

    if (t < 24) {
        if (t == 0) {
            Jl[0][0] = 0.f; Jl[0][1] = 0.f; Jl[0][2] = 0.f;
        } else {
            int j = t - 1;
            float mn0 = 3.4e38f, mn1 = 3.4e38f, mn2 = 3.4e38f;
            float mx0 = -3.4e38f, mx1 = -3.4e38f, mx2 = -3.4e38f;
            #pragma unroll
            for (int ch = 0; ch < 4; ch++) {
                const float* s = g_part + ((size_t)(j * 4 + ch) * 64 + b) * 6;
                mn0 = fminf(mn0, s[0]); mn1 = fminf(mn1, s[1]); mn2 = fminf(mn2, s[2]);
                mx0 = fmaxf(mx0, s[3]); mx1 = fmaxf(mx1, s[4]); mx2 = fmaxf(mx2, s[5]);
            }
            Jl[t][0] = 0.5f * (mn0 + mx0);
            Jl[t][1] = 0.5f * (mn1 + mx1);
            Jl[t][2] = 0.5f * (mn2 + mx2);
        }

        float rx = pose[b * 72 + t * 3 + 0];
        float ry = pose[b * 72 + t * 3 + 1];
        float rz = pose[b * 72 + t * 3 + 2];
        float th = sqrtf(rx * rx + ry * ry + rz * rz);
        th = fmaxf(th, 1e-6f);
        float s, c;
        sincosf(th, &s, &c);
        float inv = 1.0f / th;
        float x = rx * inv, y = ry * inv, z = rz * inv;
        float omc = 1.0f - c;
        R[t][0] = c + omc * x * x;     R[t][1] = omc * x * y - s * z; R[t][2] = omc * x * z + s * y;
        R[t][3] = omc * x * y + s * z; R[t][4] = c + omc * y * y;     R[t][5] = omc * y * z - s * x;
        R[t][6] = omc * x * z - s * y; R[t][7] = omc * y * z + s * x; R[t][8] = c + omc * z * z;
    }
    __syncthreads();

    if (t == 0) {
        for (int q = 0; q < 9; q++) Gr[0][q] = R[0][q];
        Gt[0][0] = Jl[0][0]; Gt[0][1] = Jl[0][1]; Gt[0][2] = Jl[0][2];
        for (int i = 1; i < 24; i++) {
            int p = (i - 1) >> 1;
            for (int r = 0; r < 3; r++)
                for (int cc = 0; cc < 3; cc++)
                    Gr[i][r * 3 + cc] = Gr[p][r * 3 + 0] * R[i][0 + cc]
                                      + Gr[p][r * 3 + 1] * R[i][3 + cc]
                                      + Gr[p][r * 3 + 2] * R[i][6 + cc];
            float dx = Jl[i][0] - Jl[p][0];
            float dy = Jl[i][1] - Jl[p][1];
            float dz = Jl[i][2] - Jl[p][2];
            for (int r = 0; r < 3; r++)
                Gt[i][r] = Gr[p][r * 3 + 0] * dx + Gr[p][r * 3 + 1] * dy
                         + Gr[p][r * 3 + 2] * dz + Gt[p][r];
        }
    }
    __syncthreads();

    if (t < 24) {
        float* d = g_G1 + ((size_t)b * 24 + t) * 12;
        for (int r = 0; r < 3; r++) {
            float tc = Gr[t][r * 3 + 0] * Jl[t][0] + Gr[t][r * 3 + 1] * Jl[t][1]
                     + Gr[t][r * 3 + 2] * Jl[t][2];
            d[r * 4 + 0] = Gr[t][r * 3 + 0];
            d[r * 4 + 1] = Gr[t][r * 3 + 1];
            d[r * 4 + 2] = Gr[t][r * 3 + 2];
            d[r * 4 + 3] = Gt[t][r] - tc;
        }
    }
}

// ---------------- Kernel B: tf32-mma shape blend + fp32 skinning (R10) ----------
// grid (1250, 2), block (32, 8) = 256 threads (8 warps), 4 vertices/thread.
#define SM_G1    0
#define SM_W     9216
#define SM_BETA  (SM_W + 768)            // 9984
#define SM_SD    (SM_BETA + 32 * 132)    // 14208
#define SM_TOT   (SM_SD + 104 * 104)     // 25024 floats = 100096 B

__global__ __launch_bounds__(256, 2) void k_main(
    const float* __restrict__ beta, const float* __restrict__ trans,
    const float* __restrict__ sd, const float* __restrict__ vt,
    const float* __restrict__ wts, float* __restrict__ out)
{
    extern __shared__ float sm[];
    float* g1_s   = sm + SM_G1;
    float* w_s    = sm + SM_W;
    float* beta_s = sm + SM_BETA;
    float* sd_s   = sm + SM_SD;

    int tid = threadIdx.y * 32 + threadIdx.x;
    int n0 = blockIdx.x * 32;
    int b0 = blockIdx.y * 32;

    uint32_t sd_sm_u32 = (uint32_t)__cvta_generic_to_shared(sd_s);

    // ---- stage sd tile [100 rows][96 cols] via cp.async, pitch 104 ----
    {
        const float* base = sd + 3 * n0;
        for (int i = tid; i < 2400; i += 256) {
            int row = i / 24, q = i - row * 24;
            cp16(sd_sm_u32 + (uint32_t)(row * 416 + q * 16),
                 base + (size_t)row * 120000 + q * 4);
        }
        cp_commit();
    }
    // zero K-pad rows 100..103
    for (int i = tid; i < 96; i += 256) {
        int r = 100 + i / 24, q = i - (i / 24) * 24;
        ((float4*)sd_s)[r * 26 + q] = make_float4(0.f, 0.f, 0.f, 0.f);
    }

    // ---- stage beta tf32 [32][132], K pad 100->104 ----
    for (int i = tid; i < 3328; i += 256) {
        int m = i / 104, k = i - m * 104;
        float v = (k < 100) ? beta[(size_t)(b0 + m) * 100 + k] : 0.f;
        beta_s[m * 132 + k] = __uint_as_float(f2tf32(v));
    }

    // ---- stage G1 + weights ----
    for (int i = tid; i < 2304; i += 256) {
        int bb = i / 72, r = i - bb * 72;
        int k = r / 3, j4 = r - k * 3;
        ((float4*)g1_s)[(k * 32 + bb) * 3 + j4] =
            *(const float4*)(g_G1 + (size_t)(b0 + bb) * 288 + r * 4);
    }
    for (int i = tid; i < 768; i += 256) {
        int k = i >> 5, vl = i & 31;
        w_s[k * 32 + vl] = wts[(size_t)(n0 + vl) * 24 + k];
    }

    cp_wait<0>();
    __syncthreads();

    // ---- tf32 mma blend: warp w -> mtile = w>>2, ntiles {3*(w&3) .. +2} ----
    int wid  = threadIdx.y;
    int lane = threadIdx.x;
    int gid  = lane >> 2, tig = lane & 3;
    int mtile = wid >> 2;
    int ntile0 = (wid & 3) * 3;

    float c[3][4];
    #pragma unroll
    for (int t = 0; t < 3; t++)
        #pragma unroll
        for (int q = 0; q < 4; q++) c[t][q] = 0.f;

    const float* ap = beta_s + (mtile * 16 + gid) * 132 + tig;
    const float* bp = sd_s + tig * 104 + ntile0 * 8 + gid;

    #pragma unroll
    for (int ks = 0; ks < 13; ks++) {
        int ko = ks * 8;
        uint32_t a0 = __float_as_uint(ap[ko]);
        uint32_t a1 = __float_as_uint(ap[ko + 8 * 132]);
        uint32_t a2 = __float_as_uint(ap[ko + 4]);
        uint32_t a3 = __float_as_uint(ap[ko + 4 + 8 * 132]);
        const float* bk = bp + ko * 104;
        uint32_t b00 = __float_as_uint(bk[0]);
        uint32_t b01 = __float_as_uint(bk[4 * 104]);
        uint32_t b10 = __float_as_uint(bk[8]);
        uint32_t b11 = __float_as_uint(bk[8 + 4 * 104]);
        uint32_t b20 = __float_as_uint(bk[16]);
        uint32_t b21 = __float_as_uint(bk[16 + 4 * 104]);
        mma_tf32(c[0], a0, a1, a2, a3, b00, b01);
        mma_tf32(c[1], a0, a1, a2, a3, b10, b11);
        mma_tf32(c[2], a0, a1, a2, a3, b20, b21);
    }

    __syncthreads();   // all sd reads done; safe to overwrite with vp

    // ---- redistribute D -> vp[m=batch][pitch 100] ----
    {
        float* vp = sd_s;
        int mrow = mtile * 16 + gid;
        #pragma unroll
        for (int t = 0; t < 3; t++) {
            int ncol = (ntile0 + t) * 8 + 2 * tig;
            *(float2*)(vp + mrow * 100 + ncol)       = make_float2(c[t][0], c[t][1]);
            *(float2*)(vp + (mrow + 8) * 100 + ncol) = make_float2(c[t][2], c[t][3]);
        }
    }
    __syncthreads();

    // ---- epilogue: acc = vp + vt, then fp32 skinning ----
    int b = threadIdx.x, vl0 = threadIdx.y * 4;

    float acc[12];
    {
        const float4* vprow = (const float4*)(sd_s + b * 100 + vl0 * 3);
        const float4* v4 = (const float4*)(vt + (size_t)(n0 + vl0) * 3);
        float4 p0 = vprow[0], p1 = vprow[1], p2 = vprow[2];
        float4 a = v4[0], b4 = v4[1], c4 = v4[2];
        acc[0] = p0.x + a.x;  acc[1] = p0.y + a.y;  acc[2]  = p0.z + a.z;  acc[3]  = p0.w + a.w;
        acc[4] = p1.x + b4.x; acc[5] = p1.y + b4.y; acc[6]  = p1.z + b4.z; acc[7]  = p1.w + b4.w;
        acc[8] = p2.x + c4.x; acc[9] = p2.y + c4.y; acc[10] = p2.z + c4.z; acc[11] = p2.w + c4.w;
    }

    float tr0 = trans[(b0 + b) * 3 + 0];
    float tr1 = trans[(b0 + b) * 3 + 1];
    float tr2 = trans[(b0 + b) * 3 + 2];
    float o[12] = {tr0, tr1, tr2, tr0, tr1, tr2, tr0, tr1, tr2, tr0, tr1, tr2};

    #pragma unroll 4
    for (int k = 0; k < 24; k++) {
        const float4* g = (const float4*)(g1_s + (k * 32 + b) * 12);
        float4 g0 = g[0], g1v = g[1], g2 = g[2];
        float4 w4 = *(const float4*)(w_s + k * 32 + vl0);
        float wv[4] = {w4.x, w4.y, w4.z, w4.w};
        #pragma unroll
        for (int vi = 0; vi < 4; vi++) {
            float vx = acc[vi * 3 + 0], vy = acc[vi * 3 + 1], vz = acc[vi * 3 + 2];
            float t0 = fmaf(g0.x,  vx, fmaf(g0.y,  vy, fmaf(g0.z,  vz, g0.w)));
            float t1 = fmaf(g1v.x, vx, fmaf(g1v.y, vy, fmaf(g1v.z, vz, g1v.w)));
            float t2 = fmaf(g2.x,  vx, fmaf(g2.y,  vy, fmaf(g2.z,  vz, g2.w)));
            o[vi * 3 + 0] = fmaf(wv[vi], t0, o[vi * 3 + 0]);
            o[vi * 3 + 1] = fmaf(wv[vi], t1, o[vi * 3 + 1]);
            o[vi * 3 + 2] = fmaf(wv[vi], t2, o[vi * 3 + 2]);
        }
    }

    float4* dst = (float4*)(out + ((size_t)(b0 + b) * 40000 + n0 + vl0) * 3);
    dst[0] = make_float4(o[0], o[1], o[2],  o[3]);
    dst[1] = make_float4(o[4], o[5], o[6],  o[7]);
    dst[2] = make_float4(o[8], o[9], o[10], o[11]);
}

// ---------------- Kernel C: skeleton partials + fused final reduction -----------
// grid (30, 8), block (64 batches, 8) = 512 threads; 2 verts/thread.
__global__ __launch_bounds__(512) void k_skel_part(
    const int* __restrict__ joint_idx, const int* __restrict__ add_idx,
    float* __restrict__ out)
{
    int j = blockIdx.x, ch = blockIdx.y;
    const int* row = (j < 23) ? (joint_idx + j * 128) : (add_idx + (j - 23) * 128);

    __shared__ int vs[16];
    __shared__ int ticket;
    int tid = threadIdx.y * 64 + threadIdx.x;
    if (tid < 16) vs[tid] = row[ch * 16 + tid];
    __syncthreads();

    int b = threadIdx.x, q = threadIdx.y;
    float mn0 = 3.4e38f, mn1 = 3.4e38f, mn2 = 3.4e38f;
    float mx0 = -3.4e38f, mx1 = -3.4e38f, mx2 = -3.4e38f;
    #pragma unroll
    for (int i = 0; i < 2; i++) {
        int v = vs[q * 2 + i];
        const float* p = out + ((size_t)b * 40000 + v) * 3;
        float x = p[0], y = p[1], z = p[2];
        mn0 = fminf(mn0, x); mx0 = fmaxf(mx0, x);
        mn1 = fminf(mn1, y); mx1 = fmaxf(mx1, y);
        mn2 = fminf(mn2, z); mx2 = fmaxf(mx2, z);
    }
    __shared__ float red[8][64][6];
    red[q][b][0] = mn0; red[q][b][1] = mn1; red[q][b][2] = mn2;
    red[q][b][3] = mx0; red[q][b][4] = mx1; red[q][b][5] = mx2;
    __syncthreads();
    if (q == 0) {
        #pragma unroll
        for (int c = 1; c < 8; c++) {
            mn0 = fminf(mn0, red[c][b][0]); mn1 = fminf(mn1, red[c][b][1]); mn2 = fminf(mn2, red[c][b][2]);
            mx0 = fmaxf(mx0, red[c][b][3]); mx1 = fmaxf(mx1, red[c][b][4]); mx2 = fmaxf(mx2, red[c][b][5]);
        }
        float* dst = g_spart + ((size_t)(j * 8 + ch) * 64 + b) * 6;
        dst[0] = mn0; dst[1] = mn1; dst[2] = mn2;
        dst[3] = mx0; dst[4] = mx1; dst[5] = mx2;
    }

    // threadfence-reduction handoff: last block of the 8 chunks finalizes row j
    __threadfence();
    __syncthreads();
    if (tid == 0) ticket = atomicAdd(&g_cnt[j], 1);
    __syncthreads();
    if (ticket == 7) {
        __threadfence();
        if (q == 0) {
            int orow = (j < 23) ? (1 + j) : (24 + (j - 23));
            float fn0 = 3.4e38f, fn1 = 3.4e38f, fn2 = 3.4e38f;
            float fx0 = -3.4e38f, fx1 = -3.4e38f, fx2 = -3.4e38f;
            #pragma unroll
            for (int c = 0; c < 8; c++) {
                const float* s = g_spart + ((size_t)(j * 8 + c) * 64 + b) * 6;
                fn0 = fminf(fn0, s[0]); fn1 = fminf(fn1, s[1]); fn2 = fminf(fn2, s[2]);
                fx0 = fmaxf(fx0, s[3]); fx1 = fmaxf(fx1, s[4]); fx2 = fmaxf(fx2, s[5]);
            }
            float* s = out + SKEL_OFF + ((size_t)b * 31 + orow) * 3;
            s[0] = 0.5f * (fn0 + fx0);
            s[1] = 0.5f * (fn1 + fx1);
            s[2] = 0.5f * (fn2 + fx2);
            if (j == 0) {
                float* z0 = out + SKEL_OFF + (size_t)b * 31 * 3;
                z0[0] = 0.f; z0[1] = 0.f; z0[2] = 0.f;
            }
        }
        if (tid == 0) atomicExch(&g_cnt[j], 0);   // reset for next graph replay
    }
}

// ---------------- launch ----------------
extern "C" void kernel_launch(void* const* d_in, const int* in_sizes, int n_in,
                              void* d_out, int out_size)
{
    const float* beta      = (const float*)d_in[0];
    const float* pose      = (const float*)d_in[1];
    const float* trans     = (const float*)d_in[2];
    const float* sd        = (const float*)d_in[3];
    const float* vt        = (const float*)d_in[4];
    const float* wts       = (const float*)d_in[5];
    const int*   joint_idx = (const int*)d_in[8];
    const int*   add_idx   = (const int*)d_in[9];
    float* out = (float*)d_out;

    cudaFuncSetAttribute(k_joint_gather, cudaFuncAttributeMaxDynamicSharedMemorySize, 64000);
    cudaFuncSetAttribute(k_main,         cudaFuncAttributeMaxDynamicSharedMemorySize, SM_TOT * 4);

    k_joint_gather<<<dim3(23, 4), dim3(32, 16), 64000>>>(beta, sd, vt, joint_idx);
    k_chain<<<64, 32>>>(pose);
    k_main<<<dim3(1250, 2), dim3(32, 8), SM_TOT * 4>>>(beta, trans, sd, vt, wts, out);
    k_skel_part<<<dim3(30, 8), dim3(64, 8)>>>(joint_idx, add_idx, out);
}

// round 17
// speedup vs baseline: 1.4979x; 1.1183x over previous
#include <cuda_runtime.h>
#include <math.h>
#include <stdint.h>

#define B_   64
#define NV   40000
#define P_   100
#define NJ   24
#define SKEL_OFF 7680000   // 64*40000*3

// ---------------- scratch (device globals; no allocation allowed) ----------------
__device__ float g_G1[B_ * NJ * 12];
__device__ float g_part[23 * 4 * B_ * 6];
__device__ float g_spart[30 * 8 * B_ * 6];
__device__ int   g_cnt[30];   // zero-initialized; returns to 0 after each replay

// ---------------- cp.async helpers ----------------
__device__ __forceinline__ void cp16(uint32_t dst, const void* src) {
    asm volatile("cp.async.cg.shared.global [%0], [%1], 16;" :: "r"(dst), "l"(src));
}
__device__ __forceinline__ void cp_commit() {
    asm volatile("cp.async.commit_group;");
}
template <int N>
__device__ __forceinline__ void cp_wait() {
    asm volatile("cp.async.wait_group %0;" :: "n"(N));
}

// ---------------- tf32 mma helpers ----------------
__device__ __forceinline__ uint32_t f2tf32(float f) {
    uint32_t u; asm("cvt.rna.tf32.f32 %0, %1;" : "=r"(u) : "f"(f)); return u;
}
__device__ __forceinline__ void mma_tf32(float c[4],
    uint32_t a0, uint32_t a1, uint32_t a2, uint32_t a3,
    uint32_t b0, uint32_t b1)
{
    asm volatile(
        "mma.sync.aligned.m16n8k8.row.col.f32.tf32.tf32.f32 "
        "{%0,%1,%2,%3},{%4,%5,%6,%7},{%8,%9},{%0,%1,%2,%3};"
        : "+f"(c[0]), "+f"(c[1]), "+f"(c[2]), "+f"(c[3])
        : "r"(a0), "r"(a1), "r"(a2), "r"(a3), "r"(b0), "r"(b1));
}

// ---------------- Kernel A1: gathered v_posed + per-chunk min/max ----------------
// grid (23 joints, 4 chunks), block (32 idx-lanes, 16) = 512 threads.
__global__ __launch_bounds__(512) void k_joint_gather(
    const float* __restrict__ beta, const float* __restrict__ sd,
    const float* __restrict__ vt, const int* __restrict__ joint_idx)
{
    extern __shared__ float sm[];
    float* beta_s = sm;          // [64][100]
    float* sd_cs  = sm + 6400;   // [100][96]
    __shared__ int idxs[32];

    int j = blockIdx.x, ch = blockIdx.y;
    int tid = threadIdx.y * 32 + threadIdx.x;

    if (tid < 32) idxs[tid] = joint_idx[j * 128 + ch * 32 + tid];
    for (int i = tid; i < 6400; i += 512) beta_s[i] = beta[i];
    __syncthreads();

    for (int i = tid; i < 3200; i += 512) {
        int p = i >> 5, s = i & 31;
        size_t base = (size_t)p * 120000 + 3 * idxs[s];
        sd_cs[p * 96 + s * 3 + 0] = sd[base + 0];
        sd_cs[p * 96 + s * 3 + 1] = sd[base + 1];
        sd_cs[p * 96 + s * 3 + 2] = sd[base + 2];
    }
    __syncthreads();

    int lane = threadIdx.x, y = threadIdx.y;
    float acc[12];
    #pragma unroll
    for (int t = 0; t < 12; t++) acc[t] = 0.f;

    for (int p = 0; p < 100; p++) {
        float s0 = sd_cs[p * 96 + lane * 3 + 0];
        float s1 = sd_cs[p * 96 + lane * 3 + 1];
        float s2 = sd_cs[p * 96 + lane * 3 + 2];
        #pragma unroll
        for (int bb = 0; bb < 4; bb++) {
            float bp = beta_s[(y * 4 + bb) * 100 + p];
            acc[bb * 3 + 0] = fmaf(bp, s0, acc[bb * 3 + 0]);
            acc[bb * 3 + 1] = fmaf(bp, s1, acc[bb * 3 + 1]);
            acc[bb * 3 + 2] = fmaf(bp, s2, acc[bb * 3 + 2]);
        }
    }
    int myidx = idxs[lane];
    float v0 = vt[3 * myidx + 0], v1 = vt[3 * myidx + 1], v2 = vt[3 * myidx + 2];
    #pragma unroll
    for (int bb = 0; bb < 4; bb++) {
        acc[bb * 3 + 0] += v0; acc[bb * 3 + 1] += v1; acc[bb * 3 + 2] += v2;
    }
    float mx[12];
    #pragma unroll
    for (int t = 0; t < 12; t++) mx[t] = acc[t];

    for (int off = 16; off; off >>= 1) {
        #pragma unroll
        for (int t = 0; t < 12; t++) {
            float om = __shfl_xor_sync(0xffffffffu, acc[t], off);
            float ox = __shfl_xor_sync(0xffffffffu, mx[t],  off);
            acc[t] = fminf(acc[t], om);
            mx[t]  = fmaxf(mx[t],  ox);
        }
    }
    if (lane < 4) {
        int b = y * 4 + lane;
        float* dst = g_part + ((size_t)(j * 4 + ch) * 64 + b) * 6;
        dst[0] = acc[lane * 3 + 0]; dst[1] = acc[lane * 3 + 1]; dst[2] = acc[lane * 3 + 2];
        dst[3] = mx[lane * 3 + 0];  dst[4] = mx[lane * 3 + 1];  dst[5] = mx[lane * 3 + 2];
    }
}

// ---------------- Kernel A2: chunk-reduce + Rodrigues + kinematic chain -> G1 ----
__global__ void k_chain(const float* __restrict__ pose)
{
    int b = blockIdx.x, t = threadIdx.x;
    __shared__ float R[24][9], Jl[24][3], Gr[24][9], Gt[24][3];

    if (t < 24) {
        if (t == 0) {
            Jl[0][0] = 0.f; Jl[0][1] = 0.f; Jl[0][2] = 0.f;
        } else {
            int j = t - 1;
            float mn0 = 3.4e38f, mn1 = 3.4e38f, mn2 = 3.4e38f;
            float mx0 = -3.4e38f, mx1 = -3.4e38f, mx2 = -3.4e38f;
            #pragma unroll
            for (int ch = 0; ch < 4; ch++) {
                const float* s = g_part + ((size_t)(j * 4 + ch) * 64 + b) * 6;
                mn0 = fminf(mn0, s[0]); mn1 = fminf(mn1, s[1]); mn2 = fminf(mn2, s[2]);
                mx0 = fmaxf(mx0, s[3]); mx1 = fmaxf(mx1, s[4]); mx2 = fmaxf(mx2, s[5]);
            }
            Jl[t][0] = 0.5f * (mn0 + mx0);
            Jl[t][1] = 0.5f * (mn1 + mx1);
            Jl[t][2] = 0.5f * (mn2 + mx2);
        }

        float rx = pose[b * 72 + t * 3 + 0];
        float ry = pose[b * 72 + t * 3 + 1];
        float rz = pose[b * 72 + t * 3 + 2];
        float th = sqrtf(rx * rx + ry * ry + rz * rz);
        th = fmaxf(th, 1e-6f);
        float s, c;
        sincosf(th, &s, &c);
        float inv = 1.0f / th;
        float x = rx * inv, y = ry * inv, z = rz * inv;
        float omc = 1.0f - c;
        R[t][0] = c + omc * x * x;     R[t][1] = omc * x * y - s * z; R[t][2] = omc * x * z + s * y;
        R[t][3] = omc * x * y + s * z; R[t][4] = c + omc * y * y;     R[t][5] = omc * y * z - s * x;
        R[t][6] = omc * x * z - s * y; R[t][7] = omc * y * z + s * x; R[t][8] = c + omc * z * z;
    }
    __syncthreads();

    if (t == 0) {
        for (int q = 0; q < 9; q++) Gr[0][q] = R[0][q];
        Gt[0][0] = Jl[0][0]; Gt[0][1] = Jl[0][1]; Gt[0][2] = Jl[0][2];
        for (int i = 1; i < 24; i++) {
            int p = (i - 1) >> 1;
            for (int r = 0; r < 3; r++)
                for (int cc = 0; cc < 3; cc++)
                    Gr[i][r * 3 + cc] = Gr[p][r * 3 + 0] * R[i][0 + cc]
                                      + Gr[p][r * 3 + 1] * R[i][3 + cc]
                                      + Gr[p][r * 3 + 2] * R[i][6 + cc];
            float dx = Jl[i][0] - Jl[p][0];
            float dy = Jl[i][1] - Jl[p][1];
            float dz = Jl[i][2] - Jl[p][2];
            for (int r = 0; r < 3; r++)
                Gt[i][r] = Gr[p][r * 3 + 0] * dx + Gr[p][r * 3 + 1] * dy
                         + Gr[p][r * 3 + 2] * dz + Gt[p][r];
        }
    }
    __syncthreads();

    if (t < 24) {
        float* d = g_G1 + ((size_t)b * 24 + t) * 12;
        for (int r = 0; r < 3; r++) {
            float tc = Gr[t][r * 3 + 0] * Jl[t][0] + Gr[t][r * 3 + 1] * Jl[t][1]
                     + Gr[t][r * 3 + 2] * Jl[t][2];
            d[r * 4 + 0] = Gr[t][r * 3 + 0];
            d[r * 4 + 1] = Gr[t][r * 3 + 1];
            d[r * 4 + 2] = Gr[t][r * 3 + 2];
            d[r * 4 + 3] = Gt[t][r] - tc;
        }
    }
}

// ---------------- Kernel B: sd-tile-reuse, tf32 blend + skinning, 2 halves ------
// grid (1250), block (32, 8). One sd tile serves BOTH batch halves.
// smem (floats): g1[24][32][12]=9216 | w[768] | beta/vp union [32][132]=4224 | sd[104][104]=10816
#define SM_G1    0
#define SM_W     9216
#define SM_BETA  (SM_W + 768)            // 9984  (vp[32][100] aliases this slot)
#define SM_SD    (SM_BETA + 32 * 132)    // 14208
#define SM_TOT   (SM_SD + 104 * 104)     // 25024 floats = 100096 B

__global__ __launch_bounds__(256, 2) void k_main(
    const float* __restrict__ beta, const float* __restrict__ trans,
    const float* __restrict__ sd, const float* __restrict__ vt,
    const float* __restrict__ wts, float* __restrict__ out)
{
    extern __shared__ float sm[];
    float* g1_s   = sm + SM_G1;
    float* w_s    = sm + SM_W;
    float* beta_s = sm + SM_BETA;   // aliased as vp after mma
    float* sd_s   = sm + SM_SD;

    int tid = threadIdx.y * 32 + threadIdx.x;
    int n0 = blockIdx.x * 32;

    uint32_t sd_sm_u32 = (uint32_t)__cvta_generic_to_shared(sd_s);

    // ---- stage sd tile ONCE via cp.async, pitch 104 ----
    {
        const float* base = sd + 3 * n0;
        for (int i = tid; i < 2400; i += 256) {
            int row = i / 24, q = i - row * 24;
            cp16(sd_sm_u32 + (uint32_t)(row * 416 + q * 16),
                 base + (size_t)row * 120000 + q * 4);
        }
        cp_commit();
    }
    // zero K-pad rows 100..103
    for (int i = tid; i < 96; i += 256) {
        int r = 100 + i / 24, q = i - (i / 24) * 24;
        ((float4*)sd_s)[r * 26 + q] = make_float4(0.f, 0.f, 0.f, 0.f);
    }
    // ---- stage weights once (depends on n0 only) ----
    for (int i = tid; i < 768; i += 256) {
        int k = i >> 5, vl = i & 31;
        w_s[k * 32 + vl] = wts[(size_t)(n0 + vl) * 24 + k];
    }

    int wid  = threadIdx.y;
    int lane = threadIdx.x;
    int gid  = lane >> 2, tig = lane & 3;
    int mtile = wid >> 2;
    int ntile0 = (wid & 3) * 3;
    int b = threadIdx.x, vl0 = threadIdx.y * 4;

    bool sd_ready = false;

    #pragma unroll
    for (int h = 0; h < 2; h++) {
        int b0 = h * 32;

        // ---- stage beta tf32 [32][132] for this half ----
        for (int i = tid; i < 3328; i += 256) {
            int m = i / 104, k = i - m * 104;
            float v = (k < 100) ? beta[(size_t)(b0 + m) * 100 + k] : 0.f;
            beta_s[m * 132 + k] = __uint_as_float(f2tf32(v));
        }
        // ---- stage G1 for this half ----
        for (int i = tid; i < 2304; i += 256) {
            int bb = i / 72, r = i - bb * 72;
            int k = r / 3, j4 = r - k * 3;
            ((float4*)g1_s)[(k * 32 + bb) * 3 + j4] =
                *(const float4*)(g_G1 + (size_t)(b0 + bb) * 288 + r * 4);
        }
        if (!sd_ready) { cp_wait<0>(); sd_ready = true; }
        __syncthreads();

        // ---- tf32 mma blend ----
        float c[3][4];
        #pragma unroll
        for (int t = 0; t < 3; t++)
            #pragma unroll
            for (int q = 0; q < 4; q++) c[t][q] = 0.f;

        const float* ap = beta_s + (mtile * 16 + gid) * 132 + tig;
        const float* bp = sd_s + tig * 104 + ntile0 * 8 + gid;

        #pragma unroll
        for (int ks = 0; ks < 13; ks++) {
            int ko = ks * 8;
            uint32_t a0 = __float_as_uint(ap[ko]);
            uint32_t a1 = __float_as_uint(ap[ko + 8 * 132]);
            uint32_t a2 = __float_as_uint(ap[ko + 4]);
            uint32_t a3 = __float_as_uint(ap[ko + 4 + 8 * 132]);
            const float* bk = bp + ko * 104;
            uint32_t b00 = __float_as_uint(bk[0]);
            uint32_t b01 = __float_as_uint(bk[4 * 104]);
            uint32_t b10 = __float_as_uint(bk[8]);
            uint32_t b11 = __float_as_uint(bk[8 + 4 * 104]);
            uint32_t b20 = __float_as_uint(bk[16]);
            uint32_t b21 = __float_as_uint(bk[16 + 4 * 104]);
            mma_tf32(c[0], a0, a1, a2, a3, b00, b01);
            mma_tf32(c[1], a0, a1, a2, a3, b10, b11);
            mma_tf32(c[2], a0, a1, a2, a3, b20, b21);
        }
        __syncthreads();   // all beta reads done; safe to overwrite slot with vp

        // ---- redistribute D -> vp[m=batch][pitch 100] (vp aliases beta slot) ----
        {
            float* vp = beta_s;
            int mrow = mtile * 16 + gid;
            #pragma unroll
            for (int t = 0; t < 3; t++) {
                int ncol = (ntile0 + t) * 8 + 2 * tig;
                *(float2*)(vp + mrow * 100 + ncol)       = make_float2(c[t][0], c[t][1]);
                *(float2*)(vp + (mrow + 8) * 100 + ncol) = make_float2(c[t][2], c[t][3]);
            }
        }
        __syncthreads();

        // ---- epilogue: acc = vp + vt, then fp32 skinning ----
        float acc[12];
        {
            const float4* vprow = (const float4*)(beta_s + b * 100 + vl0 * 3);
            const float4* v4 = (const float4*)(vt + (size_t)(n0 + vl0) * 3);
            float4 p0 = vprow[0], p1 = vprow[1], p2 = vprow[2];
            float4 a = v4[0], b4 = v4[1], c4 = v4[2];
            acc[0] = p0.x + a.x;  acc[1] = p0.y + a.y;  acc[2]  = p0.z + a.z;  acc[3]  = p0.w + a.w;
            acc[4] = p1.x + b4.x; acc[5] = p1.y + b4.y; acc[6]  = p1.z + b4.z; acc[7]  = p1.w + b4.w;
            acc[8] = p2.x + c4.x; acc[9] = p2.y + c4.y; acc[10] = p2.z + c4.z; acc[11] = p2.w + c4.w;
        }

        float tr0 = trans[(b0 + b) * 3 + 0];
        float tr1 = trans[(b0 + b) * 3 + 1];
        float tr2 = trans[(b0 + b) * 3 + 2];
        float o[12] = {tr0, tr1, tr2, tr0, tr1, tr2, tr0, tr1, tr2, tr0, tr1, tr2};

        #pragma unroll 4
        for (int k = 0; k < 24; k++) {
            const float4* g = (const float4*)(g1_s + (k * 32 + b) * 12);
            float4 g0 = g[0], g1v = g[1], g2 = g[2];
            float4 w4 = *(const float4*)(w_s + k * 32 + vl0);
            float wv[4] = {w4.x, w4.y, w4.z, w4.w};
            #pragma unroll
            for (int vi = 0; vi < 4; vi++) {
                float vx = acc[vi * 3 + 0], vy = acc[vi * 3 + 1], vz = acc[vi * 3 + 2];
                float t0 = fmaf(g0.x,  vx, fmaf(g0.y,  vy, fmaf(g0.z,  vz, g0.w)));
                float t1 = fmaf(g1v.x, vx, fmaf(g1v.y, vy, fmaf(g1v.z, vz, g1v.w)));
                float t2 = fmaf(g2.x,  vx, fmaf(g2.y,  vy, fmaf(g2.z,  vz, g2.w)));
                o[vi * 3 + 0] = fmaf(wv[vi], t0, o[vi * 3 + 0]);
                o[vi * 3 + 1] = fmaf(wv[vi], t1, o[vi * 3 + 1]);
                o[vi * 3 + 2] = fmaf(wv[vi], t2, o[vi * 3 + 2]);
            }
        }

        float4* dst = (float4*)(out + ((size_t)(b0 + b) * 40000 + n0 + vl0) * 3);
        dst[0] = make_float4(o[0], o[1], o[2],  o[3]);
        dst[1] = make_float4(o[4], o[5], o[6],  o[7]);
        dst[2] = make_float4(o[8], o[9], o[10], o[11]);

        __syncthreads();   // vp/g1 reads done before next half restages
    }
}

// ---------------- Kernel C: skeleton partials + fused final reduction -----------
// grid (30, 8), block (64 batches, 8) = 512 threads; 2 verts/thread.
__global__ __launch_bounds__(512) void k_skel_part(
    const int* __restrict__ joint_idx, const int* __restrict__ add_idx,
    float* __restrict__ out)
{
    int j = blockIdx.x, ch = blockIdx.y;
    const int* row = (j < 23) ? (joint_idx + j * 128) : (add_idx + (j - 23) * 128);

    __shared__ int vs[16];
    __shared__ int ticket;
    int tid = threadIdx.y * 64 + threadIdx.x;
    if (tid < 16) vs[tid] = row[ch * 16 + tid];
    __syncthreads();

    int b = threadIdx.x, q = threadIdx.y;
    float mn0 = 3.4e38f, mn1 = 3.4e38f, mn2 = 3.4e38f;
    float mx0 = -3.4e38f, mx1 = -3.4e38f, mx2 = -3.4e38f;
    #pragma unroll
    for (int i = 0; i < 2; i++) {
        int v = vs[q * 2 + i];
        const float* p = out + ((size_t)b * 40000 + v) * 3;
        float x = p[0], y = p[1], z = p[2];
        mn0 = fminf(mn0, x); mx0 = fmaxf(mx0, x);
        mn1 = fminf(mn1, y); mx1 = fmaxf(mx1, y);
        mn2 = fminf(mn2, z); mx2 = fmaxf(mx2, z);
    }
    __shared__ float red[8][64][6];
    red[q][b][0] = mn0; red[q][b][1] = mn1; red[q][b][2] = mn2;
    red[q][b][3] = mx0; red[q][b][4] = mx1; red[q][b][5] = mx2;
    __syncthreads();
    if (q == 0) {
        #pragma unroll
        for (int c = 1; c < 8; c++) {
            mn0 = fminf(mn0, red[c][b][0]); mn1 = fminf(mn1, red[c][b][1]); mn2 = fminf(mn2, red[c][b][2]);
            mx0 = fmaxf(mx0, red[c][b][3]); mx1 = fmaxf(mx1, red[c][b][4]); mx2 = fmaxf(mx2, red[c][b][5]);
        }
        float* dst = g_spart + ((size_t)(j * 8 + ch) * 64 + b) * 6;
        dst[0] = mn0; dst[1] = mn1; dst[2] = mn2;
        dst[3] = mx0; dst[4] = mx1; dst[5] = mx2;
    }

    __threadfence();
    __syncthreads();
    if (tid == 0) ticket = atomicAdd(&g_cnt[j], 1);
    __syncthreads();
    if (ticket == 7) {
        __threadfence();
        if (q == 0) {
            int orow = (j < 23) ? (1 + j) : (24 + (j - 23));
            float fn0 = 3.4e38f, fn1 = 3.4e38f, fn2 = 3.4e38f;
            float fx0 = -3.4e38f, fx1 = -3.4e38f, fx2 = -3.4e38f;
            #pragma unroll
            for (int c = 0; c < 8; c++) {
                const float* s = g_spart + ((size_t)(j * 8 + c) * 64 + b) * 6;
                fn0 = fminf(fn0, s[0]); fn1 = fminf(fn1, s[1]); fn2 = fminf(fn2, s[2]);
                fx0 = fmaxf(fx0, s[3]); fx1 = fmaxf(fx1, s[4]); fx2 = fmaxf(fx2, s[5]);
            }
            float* s = out + SKEL_OFF + ((size_t)b * 31 + orow) * 3;
            s[0] = 0.5f * (fn0 + fx0);
            s[1] = 0.5f * (fn1 + fx1);
            s[2] = 0.5f * (fn2 + fx2);
            if (j == 0) {
                float* z0 = out + SKEL_OFF + (size_t)b * 31 * 3;
                z0[0] = 0.f; z0[1] = 0.f; z0[2] = 0.f;
            }
        }
        if (tid == 0) atomicExch(&g_cnt[j], 0);   // reset for next graph replay
    }
}

// ---------------- launch ----------------
extern "C" void kernel_launch(void* const* d_in, const int* in_sizes, int n_in,
                              void* d_out, int out_size)
{
    const float* beta      = (const float*)d_in[0];
    const float* pose      = (const float*)d_in[1];
    const float* trans     = (const float*)d_in[2];
    const float* sd        = (const float*)d_in[3];
    const float* vt        = (const float*)d_in[4];
    const float* wts       = (const float*)d_in[5];
    const int*   joint_idx = (const int*)d_in[8];
    const int*   add_idx   = (const int*)d_in[9];
    float* out = (float*)d_out;

    cudaFuncSetAttribute(k_joint_gather, cudaFuncAttributeMaxDynamicSharedMemorySize, 64000);
    cudaFuncSetAttribute(k_main,         cudaFuncAttributeMaxDynamicSharedMemorySize, SM_TOT * 4);

    k_joint_gather<<<dim3(23, 4), dim3(32, 16), 64000>>>(beta, sd, vt, joint_idx);
    k_chain<<<64, 32>>>(pose);
    k_main<<<1250, dim3(32, 8), SM_TOT * 4>>>(beta, trans, sd, vt, wts, out);
    k_skel_part<<<dim3(30, 8), dim3(64, 8)>>>(joint_idx, add_idx, out);
}